// round 16
// baseline (speedup 1.0000x reference)
#include <cuda_runtime.h>

// RNN-T transducer loss. B=16, T=200, U=101, A=512, blank=0.
// LOG2-domain diagonal-split lattice, lazy (m,f) rep (h = m + lg2(f)),
// barrier-free shfl schedule. r16: DIAGONAL-MAJOR compact operand tables --
// all operands of wavefront step s live on one table row, so per-step
// addressing is one running base + fixed per-lane column (no clamps/IMADs).
// Junction overrun guard fixed (r15 could write past s_ja).
//   identity: log_p = LSE_{t+u=D} alpha[t,u] + beta[t,u],  D=(Tb+Ub)/2
//   Qf[d][u] = (blk[d-u][u], emit[d-u+1][u-1])          rows 0..D-1
//   Qb[dp][v] = (blk,emit) at (t,u)=(Tb-1-(dp-v),Ub-v)  rows 0..spD
// Compact triangle rows: widthF(d)=min(d+2,102), widthB(dp)=min(dp+1,102).

#define BQ 16
#define TM 200
#define UM 101
#define AA 512
#define UP 104
#define NEG (-1.0e30f)
#define LOG2E 1.4426950408889634f
#define LN2   0.6931471805599453f
#define FULL  0xffffffffu
#define NF 10450      // > baseF(149)+102
#define NB 10250      // > baseB(149)+102

__device__ __align__(16) float2 g_qf[BQ][NF];   // zero-init .bss
__device__ __align__(16) float2 g_qb[BQ][NB];
__device__ float g_logp[BQ];
__device__ int   g_cnt = 0;

__device__ __forceinline__ int baseF(int d) { return (d <= 100) ? d * (d + 3) / 2 : 5150 + (d - 100) * 102; }
__device__ __forceinline__ int baseB(int d) { return (d <= 101) ? d * (d + 1) / 2 : 5151 + (d - 101) * 102; }

__device__ __forceinline__ float ex2(float x) { float y; asm("ex2.approx.f32 %0, %1;" : "=f"(y) : "f"(x)); return y; }
__device__ __forceinline__ float lg2(float x) { float y; asm("lg2.approx.f32 %0, %1;" : "=f"(y) : "f"(x)); return y; }

__global__ void tl_gather_kernel(const float* __restrict__ lp,
                                 const int*   __restrict__ labels,
                                 const int*   __restrict__ Tarr,
                                 const int*   __restrict__ Uarr)
{
    const int total  = BQ * TM * UM;
    const int stride = gridDim.x * blockDim.x;
    int i0 = blockIdx.x * blockDim.x + threadIdx.x;
    #pragma unroll
    for (int kk = 0; kk < 4; ++kk) {
        int i = i0 + kk * stride;
        if (i < total) {
            int u  = i % UM;
            int bt = i / UM;
            int t  = bt % TM;
            int b  = bt / TM;
            int lab = (u < UM - 1) ? __ldg(labels + b * (UM - 1) + u) : 0;
            size_t base = (size_t)i * AA;
            float bv = __ldg(lp + base) * LOG2E;
            float ev = lab ? __ldg(lp + base + lab) * LOG2E : bv;
            const int Tb = __ldg(Tarr + b);
            const int Ub = __ldg(Uarr + b);
            const int D  = (Tb + Ub) >> 1;
            const int spD = Tb - 1 + Ub - D;
            const int d = t + u;
            if (d < D) {                      // forward half (diag < D)
                const int bf = baseF(d);
                g_qf[b][bf + u].x     = bv;   // blk[t][u]   -> row d, col u
                g_qf[b][bf + u + 1].y = ev;   // emit[t][u]  -> row d, col u+1
            }
            const int v  = Ub - u;
            const int dp = (Tb - 1 - t) + v;
            if (t < Tb && v >= 0 && dp <= spD)     // backward half (diag >= D)
                g_qb[b][baseB(dp) + v] = make_float2(bv, ev);
        }
    }
}

__global__ __launch_bounds__(256, 1)
void tl_lattice_kernel(const int* __restrict__ Tarr,
                       const int* __restrict__ Uarr,
                       float* __restrict__ out)
{
    extern __shared__ float2 s_q[];
    float2* s_qf = s_q;                      // [NF]
    float2* s_qb = s_q + NF;                 // [NB]
    __shared__ float s_ja[UP], s_jb[UP];

    const int b    = blockIdx.x;
    const int tid  = threadIdx.x;
    const int lane = tid & 31;
    const int wid  = tid >> 5;

    {   // stage compact tables (coalesced float4, 8 warps)
        const float4* gf = (const float4*)g_qf[b];
        const float4* gw = (const float4*)g_qb[b];
        float4* sf = (float4*)s_qf;
        float4* sw = (float4*)s_qb;
        for (int k = tid; k < NF / 2; k += 256) sf[k] = gf[k];
        for (int k = tid; k < NB / 2; k += 256) sw[k] = gw[k];
    }
    if (tid < UP) { s_ja[tid] = NEG; s_jb[tid] = NEG; }

    const int Tb  = __ldg(Tarr + b);
    const int Ub  = __ldg(Uarr + b);
    const int D   = (Tb + Ub) >> 1;
    const int spD = Tb - 1 + Ub - D;
    __syncthreads();

    const int src = (lane + 31) & 31;        // rotate-up source lane

    if (wid == 0) {
        // -------- forward alpha: steps s = 1..D read table row s-1 --------
        int uu[4], addr[4];
        #pragma unroll
        for (int j = 0; j < 4; ++j) {
            uu[j]   = lane + 32 * j;
            addr[j] = min(uu[j], 101);       // baseF(0) = 0
        }
        float M[4] = {(lane == 0) ? 0.0f : NEG, NEG, NEG, NEG};   // alpha[0,0]=0
        float f[4] = {1.f, 1.f, 1.f, 1.f};

        int s = 1;
        const int n8 = D >> 3;
        for (int b8 = 0; b8 < n8; ++b8) {
            #pragma unroll
            for (int ds = 0; ds < 8; ++ds) {
                float hm[4], hf[4];
                #pragma unroll
                for (int j = 0; j < 4; ++j) {
                    hm[j] = __shfl_sync(FULL, M[j], src);
                    hf[j] = __shfl_sync(FULL, f[j], src);
                }
                const int w = min(s + 1, 102);
                #pragma unroll
                for (int j = 0; j < 4; ++j) {
                    const float2 pv = s_qf[addr[j]];
                    const float hinm = lane ? hm[j] : (j ? hm[j - 1] : NEG);
                    const float hinf = lane ? hf[j] : (j ? hf[j - 1] : 1.0f);
                    const float verm = M[j] + pv.x;
                    const float horm = hinm + pv.y;
                    const float dd = verm - horm;
                    const float Mx = fmaxf(verm, horm);
                    const float e  = ex2(0.0f - fabsf(dd));
                    const float fb = (dd >= 0.0f) ? f[j] : hinf;
                    const float fs = (dd >= 0.0f) ? hinf : f[j];
                    f[j] = fmaf(fs, e, fb);
                    M[j] = Mx;
                    addr[j] += w;
                }
                ++s;
            }
            #pragma unroll
            for (int j = 0; j < 4; ++j) {    // exact exponent folding
                const int bi = __float_as_int(f[j]);
                const int ex = (bi >> 23) - 127;
                M[j] += (float)ex;
                f[j] = __int_as_float(bi - (ex << 23));
            }
        }
        for (; s <= D; ++s) {
            float hm[4], hf[4];
            #pragma unroll
            for (int j = 0; j < 4; ++j) {
                hm[j] = __shfl_sync(FULL, M[j], src);
                hf[j] = __shfl_sync(FULL, f[j], src);
            }
            const int w = min(s + 1, 102);
            #pragma unroll
            for (int j = 0; j < 4; ++j) {
                const float2 pv = s_qf[addr[j]];
                const float hinm = lane ? hm[j] : (j ? hm[j - 1] : NEG);
                const float hinf = lane ? hf[j] : (j ? hf[j - 1] : 1.0f);
                const float verm = M[j] + pv.x;
                const float horm = hinm + pv.y;
                const float dd = verm - horm;
                const float Mx = fmaxf(verm, horm);
                const float e  = ex2(0.0f - fabsf(dd));
                const float fb = (dd >= 0.0f) ? f[j] : hinf;
                const float fs = (dd >= 0.0f) ? hinf : f[j];
                f[j] = fmaf(fs, e, fb);
                M[j] = Mx;
                addr[j] += w;
            }
        }
        // junction cut cells (D-u, u); guard includes array bound (r15 fix)
        #pragma unroll
        for (int j = 0; j < 4; ++j) {
            const int tF = D - uu[j];
            if (tF >= 0 && tF < Tb && uu[j] <= 101)
                s_ja[uu[j]] = M[j] + lg2(f[j]);
        }
    } else if (wid == 1) {
        // -------- backward beta: steps sp = 1..spD read table row sp --------
        int vv[4], addr[4];
        #pragma unroll
        for (int j = 0; j < 4; ++j) {
            vv[j]   = lane + 32 * j;
            addr[j] = 1 + min(vv[j], 101);   // baseB(1) = 1
        }
        float M[4] = {NEG, NEG, NEG, NEG};
        float f[4] = {1.f, 1.f, 1.f, 1.f};
        if (lane == 0) M[0] = s_qb[0].x;     // beta[Tb-1,Ub] = blk[Tb-1,Ub]

        int sp = 1;
        const int n8 = spD >> 3;
        for (int b8 = 0; b8 < n8; ++b8) {
            #pragma unroll
            for (int ds = 0; ds < 8; ++ds) {
                float hm[4], hf[4];
                #pragma unroll
                for (int j = 0; j < 4; ++j) {
                    hm[j] = __shfl_sync(FULL, M[j], src);
                    hf[j] = __shfl_sync(FULL, f[j], src);
                }
                const int w = min(sp + 1, 102);
                #pragma unroll
                for (int j = 0; j < 4; ++j) {
                    const float2 pv = s_qb[addr[j]];
                    const float hinm = lane ? hm[j] : (j ? hm[j - 1] : NEG);
                    const float hinf = lane ? hf[j] : (j ? hf[j - 1] : 1.0f);
                    const float verm = M[j] + pv.x;   // beta[t+1,u] + blk[t,u]
                    const float horm = hinm + pv.y;   // beta[t,u+1] + emit[t,u]
                    const float dd = verm - horm;
                    const float Mx = fmaxf(verm, horm);
                    const float e  = ex2(0.0f - fabsf(dd));
                    const float fb = (dd >= 0.0f) ? f[j] : hinf;
                    const float fs = (dd >= 0.0f) ? hinf : f[j];
                    f[j] = fmaf(fs, e, fb);
                    M[j] = Mx;
                    addr[j] += w;
                }
                ++sp;
            }
            #pragma unroll
            for (int j = 0; j < 4; ++j) {
                const int bi = __float_as_int(f[j]);
                const int ex = (bi >> 23) - 127;
                M[j] += (float)ex;
                f[j] = __int_as_float(bi - (ex << 23));
            }
        }
        for (; sp <= spD; ++sp) {
            float hm[4], hf[4];
            #pragma unroll
            for (int j = 0; j < 4; ++j) {
                hm[j] = __shfl_sync(FULL, M[j], src);
                hf[j] = __shfl_sync(FULL, f[j], src);
            }
            const int w = min(sp + 1, 102);
            #pragma unroll
            for (int j = 0; j < 4; ++j) {
                const float2 pv = s_qb[addr[j]];
                const float hinm = lane ? hm[j] : (j ? hm[j - 1] : NEG);
                const float hinf = lane ? hf[j] : (j ? hf[j - 1] : 1.0f);
                const float verm = M[j] + pv.x;
                const float horm = hinm + pv.y;
                const float dd = verm - horm;
                const float Mx = fmaxf(verm, horm);
                const float e  = ex2(0.0f - fabsf(dd));
                const float fb = (dd >= 0.0f) ? f[j] : hinf;
                const float fs = (dd >= 0.0f) ? hinf : f[j];
                f[j] = fmaf(fs, e, fb);
                M[j] = Mx;
                addr[j] += w;
            }
        }
        // junction cut cells (t,u) = (Tb-1-(spD-v), Ub-v)
        #pragma unroll
        for (int j = 0; j < 4; ++j) {
            const int tp = spD - vv[j];
            const int u2 = Ub - vv[j];
            if (tp >= 0 && tp < Tb && u2 >= 0)
                s_jb[u2] = M[j] + lg2(f[j]);
        }
    }
    __syncthreads();

    // log_p = LN2 * LSE2_u(ja[u] + jb[u])   (warp 0)
    if (tid < 32) {
        float x0 = (tid      < UP) ? s_ja[tid]      + s_jb[tid]      : NEG;
        float x1 = (tid + 32 < UP) ? s_ja[tid + 32] + s_jb[tid + 32] : NEG;
        float x2 = (tid + 64 < UP) ? s_ja[tid + 64] + s_jb[tid + 64] : NEG;
        float x3 = (tid + 96 < UP) ? s_ja[tid + 96] + s_jb[tid + 96] : NEG;
        float mm = fmaxf(fmaxf(x0, x1), fmaxf(x2, x3));
        #pragma unroll
        for (int o = 16; o > 0; o >>= 1)
            mm = fmaxf(mm, __shfl_xor_sync(FULL, mm, o));
        float sum2 = ex2(x0 - mm) + ex2(x1 - mm) + ex2(x2 - mm) + ex2(x3 - mm);
        #pragma unroll
        for (int o = 16; o > 0; o >>= 1)
            sum2 += __shfl_xor_sync(FULL, sum2, o);
        if (tid == 0) g_logp[b] = (mm + lg2(sum2)) * LN2;
    }
    __syncthreads();

    // fixed-order mean reduction in the last-arriving CTA (deterministic)
    if (tid == 0) {
        __threadfence();
        int old = atomicAdd(&g_cnt, 1);
        if (old == BQ - 1) {
            __threadfence();
            float ssum = 0.0f;
            #pragma unroll
            for (int i = 0; i < BQ; ++i) ssum += g_logp[i];
            out[0] = -ssum / (float)BQ;
            g_cnt = 0;                       // reset for next graph replay
        }
    }
}

extern "C" void kernel_launch(void* const* d_in, const int* in_sizes, int n_in,
                              void* d_out, int out_size)
{
    const float* lp     = (const float*)d_in[0];
    const int*   labels = (const int*)  d_in[1];
    const int*   Tarr   = (const int*)  d_in[2];
    const int*   Uarr   = (const int*)  d_in[3];
    float* out = (float*)d_out;

    const int smem_bytes = (NF + NB) * (int)sizeof(float2);    // 165,600
    cudaFuncSetAttribute(tl_lattice_kernel,
                         cudaFuncAttributeMaxDynamicSharedMemorySize,
                         smem_bytes);

    const int total  = BQ * TM * UM;
    const int blocks = (total + 256 * 4 - 1) / (256 * 4);      // 316
    tl_gather_kernel<<<blocks, 256>>>(lp, labels, Tarr, Uarr);
    tl_lattice_kernel<<<BQ, 256, smem_bytes>>>(Tarr, Uarr, out);
}